// round 10
// baseline (speedup 1.0000x reference)
#include <cuda_runtime.h>
#include <cuda_bf16.h>

// Problem constants (reference shapes are fixed)
#define NN 50000
#define NE 800000
#define IN_CH 64
#define OUT_DIM 128
#define HEADS 4
#define CPH 32           // channels per head
#define NEG 0.2f
#define SCAN_TILE 512
#define MAX_BLKS ((NN + SCAN_TILE - 1) / SCAN_TILE)   // 98

// Scratch (static __device__ — allocations are forbidden)
__device__ float g_xt[NN * OUT_DIM];        // transformed features [N,128] (25.6 MB)
__device__ float g_asrc[NN * HEADS];        // per-node src attention half
__device__ float g_adst[NN * HEADS];        // per-node dst attention half
__device__ float g_linwT[IN_CH * OUT_DIM];  // lin_w transposed [k][t]
__device__ float g_reswT[IN_CH * OUT_DIM];  // res_w transposed [k][t]
__device__ int   g_deg[NN];                 // in-degree per dst
__device__ int   g_rowptr[NN];              // CSR row start
__device__ int   g_cursor[NN];              // fill cursor (== row end after fill)
__device__ int   g_srcs[NE];                // CSR column (source node ids)
__device__ int   g_bsum[128];               // per-block scan totals

__device__ __forceinline__ float lrelu(float v) { return v >= 0.f ? v : NEG * v; }
__device__ __forceinline__ int clampi(int v, int n) {
    return v < 0 ? 0 : (v >= n ? n - 1 : v);
}

// ---------------------------------------------------------------------------
// Kernel 0: transpose weights + zero degree counters
// grid = 64, block = 128
// ---------------------------------------------------------------------------
__global__ void __launch_bounds__(128) k_transpose(
    const float* __restrict__ lin_w, const float* __restrict__ res_w, int N)
{
    int k = blockIdx.x;      // 0..63
    int t = threadIdx.x;     // 0..127
    g_linwT[k * OUT_DIM + t] = lin_w[t * IN_CH + k];
    g_reswT[k * OUT_DIM + t] = res_w[t * IN_CH + k];
    for (int i = blockIdx.x * 128 + t; i < N; i += 64 * 128) g_deg[i] = 0;
}

// ---------------------------------------------------------------------------
// Kernel 1: per-node — xt = x @ lin_w^T, attention halves
// grid = N, block = 128
// ---------------------------------------------------------------------------
__global__ void __launch_bounds__(128) k_node_prep(
    const float* __restrict__ x,
    const float* __restrict__ att_src, const float* __restrict__ att_dst, int N)
{
    int n = blockIdx.x;
    int t = threadIdx.x;
    if (n >= N) return;

    __shared__ float sx[IN_CH];
    if (t < IN_CH) sx[t] = x[n * IN_CH + t];
    __syncthreads();

    float acc = 0.f;
#pragma unroll
    for (int k = 0; k < IN_CH; k++) acc += sx[k] * g_linwT[k * OUT_DIM + t];

    g_xt[n * OUT_DIM + t] = acc;

    int h = t >> 5, c = t & 31;
    float as = acc * att_src[h * CPH + c];
    float ad = acc * att_dst[h * CPH + c];
#pragma unroll
    for (int o = 16; o; o >>= 1) {
        as += __shfl_xor_sync(0xFFFFFFFFu, as, o);
        ad += __shfl_xor_sync(0xFFFFFFFFu, ad, o);
    }
    if (c == 0) {
        g_asrc[n * HEADS + h] = as;
        g_adst[n * HEADS + h] = ad;
    }
}

// ---------------------------------------------------------------------------
// Kernel 2: count in-degrees
// ---------------------------------------------------------------------------
__global__ void __launch_bounds__(256) k_count(const int* __restrict__ ei, int E, int N)
{
    int e = blockIdx.x * blockDim.x + threadIdx.x;
    if (e >= E) return;
    int d = clampi(ei[E + e], N);
    atomicAdd(&g_deg[d], 1);
}

// ---------------------------------------------------------------------------
// Kernel 3a: per-tile exclusive scan (block-local) + block totals
// grid = ceil(N/512), block = 512
// ---------------------------------------------------------------------------
__global__ void __launch_bounds__(SCAN_TILE) k_scan1(int N)
{
    int t = threadIdx.x;
    int i = blockIdx.x * SCAN_TILE + t;
    int v = (i < N) ? g_deg[i] : 0;

    int lane = t & 31, wid = t >> 5;
    int inc = v;
#pragma unroll
    for (int o = 1; o < 32; o <<= 1) {
        int u = __shfl_up_sync(0xFFFFFFFFu, inc, o);
        if (lane >= o) inc += u;
    }
    __shared__ int ws[16];
    if (lane == 31) ws[wid] = inc;
    __syncthreads();
    if (t < 16) {
        int s = ws[t];
        int inc2 = s;
#pragma unroll
        for (int o = 1; o < 16; o <<= 1) {
            int u = __shfl_up_sync(0xFFFFu, inc2, o);
            if (t >= o) inc2 += u;
        }
        ws[t] = inc2 - s;                    // exclusive warp offset
        if (t == 15) g_bsum[blockIdx.x] = inc2;   // block total
    }
    __syncthreads();
    if (i < N) g_rowptr[i] = inc - v + ws[wid];  // block-local exclusive
}

// ---------------------------------------------------------------------------
// Kernel 3b: scan block totals (single small block; NB <= 128)
// ---------------------------------------------------------------------------
__global__ void __launch_bounds__(128) k_scan2(int NB)
{
    int t = threadIdx.x;
    int v = (t < NB) ? g_bsum[t] : 0;
    __shared__ int s[128];
    s[t] = v;
    __syncthreads();
    for (int off = 1; off < 128; off <<= 1) {
        int u = (t >= off) ? s[t - off] : 0;
        __syncthreads();
        s[t] += u;
        __syncthreads();
    }
    g_bsum[t] = s[t] - v;   // exclusive block offset
}

// ---------------------------------------------------------------------------
// Kernel 3c: add block offsets, init cursors
// ---------------------------------------------------------------------------
__global__ void __launch_bounds__(SCAN_TILE) k_scan3(int N)
{
    int i = blockIdx.x * SCAN_TILE + threadIdx.x;
    if (i >= N) return;
    int r = g_rowptr[i] + g_bsum[blockIdx.x];
    g_rowptr[i] = r;
    g_cursor[i] = r;
}

// ---------------------------------------------------------------------------
// Kernel 4: fill CSR columns
// ---------------------------------------------------------------------------
__global__ void __launch_bounds__(256) k_fill(const int* __restrict__ ei, int E, int N)
{
    int e = blockIdx.x * blockDim.x + threadIdx.x;
    if (e >= E) return;
    int s = clampi(ei[e], N);
    int d = clampi(ei[E + e], N);
    int p = atomicAdd(&g_cursor[d], 1);
    g_srcs[p] = s;
}

// ---------------------------------------------------------------------------
// Kernel 5: one warp per dst node — softmax denom, weighted aggregate,
// self-loop, residual GEMV, LayerNorm, LeakyReLU, store. No atomics.
// block = 256 (8 warps = 8 nodes), grid = ceil(N/8)
// ---------------------------------------------------------------------------
__global__ void __launch_bounds__(256) k_aggregate(
    const float* __restrict__ x,
    const float* __restrict__ res_b, const float* __restrict__ gat_bias,
    const float* __restrict__ ln_g, const float* __restrict__ ln_b,
    float* __restrict__ out, int N)
{
    int w    = threadIdx.x >> 5;
    int lane = threadIdx.x & 31;
    int d = blockIdx.x * 8 + w;
    if (d >= N) return;

    int r0 = g_rowptr[d];
    int r1 = g_cursor[d];          // == row end after fill

    int hA = lane & 3;             // pass-A head (4 heads x 8 edges per iter)
    int hB = lane >> 3;            // pass-B head (lane*4 channels -> head)

    float adst_hA = g_adst[d * HEADS + hA];
    float asrc_d  = g_asrc[d * HEADS + hA];

    // ---- pass A: softmax denominator (8 edges per warp-iteration) ----
    float acc_e = 0.f;
    for (int base = r0; base < r1; base += 8) {
        int e = base + (lane >> 2);
        if (e < r1) {
            int s = g_srcs[e];
            acc_e += expf(lrelu(g_asrc[s * HEADS + hA] + adst_hA));
        }
    }
    acc_e += __shfl_xor_sync(0xFFFFFFFFu, acc_e, 4);
    acc_e += __shfl_xor_sync(0xFFFFFFFFu, acc_e, 8);
    acc_e += __shfl_xor_sync(0xFFFFFFFFu, acc_e, 16);

    float ex_self = expf(lrelu(asrc_d + adst_hA));
    float esum_hA = acc_e + ex_self;     // lanes 0..3 hold heads 0..3

    float esum_B   = __shfl_sync(0xFFFFFFFFu, esum_hA, hB);
    float adst_hB  = __shfl_sync(0xFFFFFFFFu, adst_hA, hB);
    float exself_B = __shfl_sync(0xFFFFFFFFu, ex_self, hB);
    float inv_es = 1.f / (esum_B + 1e-16f);

    // ---- pass B: weighted aggregation (1 edge per warp-iteration) ----
    float4 acc = make_float4(0.f, 0.f, 0.f, 0.f);
    for (int e = r0; e < r1; e++) {
        int s = g_srcs[e];
        float alpha = expf(lrelu(g_asrc[s * HEADS + hB] + adst_hB)) * inv_es;
        float4 v = *reinterpret_cast<const float4*>(g_xt + s * OUT_DIM + lane * 4);
        acc.x += v.x * alpha; acc.y += v.y * alpha;
        acc.z += v.z * alpha; acc.w += v.w * alpha;
    }
    // self-loop
    {
        float alpha = exself_B * inv_es;
        float4 v = *reinterpret_cast<const float4*>(g_xt + d * OUT_DIM + lane * 4);
        acc.x += v.x * alpha; acc.y += v.y * alpha;
        acc.z += v.z * alpha; acc.w += v.w * alpha;
    }

    // ---- residual GEMV (per-warp smem x row, coalesced transposed weights) ----
    __shared__ float sx[8][IN_CH];
    sx[w][lane]      = x[d * IN_CH + lane];
    sx[w][lane + 32] = x[d * IN_CH + lane + 32];
    __syncwarp();

    float4 r = make_float4(0.f, 0.f, 0.f, 0.f);
#pragma unroll
    for (int k = 0; k < IN_CH; k++) {
        float xv = sx[w][k];
        float4 wv = *reinterpret_cast<const float4*>(g_reswT + k * OUT_DIM + lane * 4);
        r.x += xv * wv.x; r.y += xv * wv.y; r.z += xv * wv.z; r.w += xv * wv.w;
    }

    int t0 = lane * 4;
    float4 gb  = *reinterpret_cast<const float4*>(gat_bias + t0);
    float4 rb  = *reinterpret_cast<const float4*>(res_b + t0);
    float4 z;
    z.x = acc.x + gb.x + r.x + rb.x;
    z.y = acc.y + gb.y + r.y + rb.y;
    z.z = acc.z + gb.z + r.z + rb.z;
    z.w = acc.w + gb.w + r.w + rb.w;

    // ---- LayerNorm over 128 (warp reduce) ----
    float sum = z.x + z.y + z.z + z.w;
#pragma unroll
    for (int o = 16; o; o >>= 1) sum += __shfl_xor_sync(0xFFFFFFFFu, sum, o);
    float mu = sum * (1.f / OUT_DIM);

    float4 zc;
    zc.x = z.x - mu; zc.y = z.y - mu; zc.z = z.z - mu; zc.w = z.w - mu;
    float vv = zc.x * zc.x + zc.y * zc.y + zc.z * zc.z + zc.w * zc.w;
#pragma unroll
    for (int o = 16; o; o >>= 1) vv += __shfl_xor_sync(0xFFFFFFFFu, vv, o);
    float rs = rsqrtf(vv * (1.f / OUT_DIM) + 1e-5f);

    float4 lg = *reinterpret_cast<const float4*>(ln_g + t0);
    float4 lb = *reinterpret_cast<const float4*>(ln_b + t0);
    float4 o4;
    o4.x = lrelu(zc.x * rs * lg.x + lb.x);
    o4.y = lrelu(zc.y * rs * lg.y + lb.y);
    o4.z = lrelu(zc.z * rs * lg.z + lb.z);
    o4.w = lrelu(zc.w * rs * lg.w + lb.w);
    *reinterpret_cast<float4*>(out + d * OUT_DIM + t0) = o4;
}

// ---------------------------------------------------------------------------
extern "C" void kernel_launch(void* const* d_in, const int* in_sizes, int n_in,
                              void* d_out, int out_size)
{
    const float* x        = (const float*)d_in[0];
    const int*   ei       = (const int*)d_in[1];     // int32 (JAX x64 disabled)
    const float* lin_w    = (const float*)d_in[2];
    const float* att_src  = (const float*)d_in[3];
    const float* att_dst  = (const float*)d_in[4];
    const float* gat_bias = (const float*)d_in[5];
    const float* res_w    = (const float*)d_in[6];
    const float* res_b    = (const float*)d_in[7];
    const float* ln_g     = (const float*)d_in[8];
    const float* ln_b     = (const float*)d_in[9];
    float* out = (float*)d_out;

    int N = in_sizes[0] / IN_CH;     // 50000
    int E = in_sizes[1] / 2;         // 800000
    if (N > NN) N = NN;              // clamp to static scratch capacity
    if (E > NE) E = NE;

    int NB = (N + SCAN_TILE - 1) / SCAN_TILE;   // <= 98

    k_transpose<<<IN_CH, 128>>>(lin_w, res_w, N);
    k_node_prep<<<N, 128>>>(x, att_src, att_dst, N);
    k_count<<<(E + 255) / 256, 256>>>(ei, E, N);
    k_scan1<<<NB, SCAN_TILE>>>(N);
    k_scan2<<<1, 128>>>(NB);
    k_scan3<<<NB, SCAN_TILE>>>(N);
    k_fill<<<(E + 255) / 256, 256>>>(ei, E, N);
    k_aggregate<<<(N + 7) / 8, 256>>>(x, res_b, gat_bias, ln_g, ln_b, out, N);
}

// round 12
// speedup vs baseline: 1.5397x; 1.5397x over previous
#include <cuda_runtime.h>
#include <cuda_bf16.h>

// Problem constants (reference shapes are fixed)
#define NN 50000
#define NE 800000
#define IN_CH 64
#define OUT_DIM 128
#define HEADS 4
#define CPH 32           // channels per head
#define NEG 0.2f
#define SCAN_TILE 512

// Scratch (static __device__ — allocations are forbidden)
__device__ float g_xt[NN * OUT_DIM];        // transformed features [N,128] (25.6 MB)
__device__ float g_asrc[NN * HEADS];        // per-node src attention half
__device__ float g_adst[NN * HEADS];        // per-node dst attention half
__device__ float g_linwT[IN_CH * OUT_DIM];  // lin_w transposed [k][t]
__device__ float g_reswT[IN_CH * OUT_DIM];  // res_w transposed [k][t]
__device__ int   g_deg[NN];                 // in-degree per dst
__device__ int   g_rowptr[NN];              // CSR row start
__device__ int   g_cursor[NN];              // fill cursor (== row end after fill)
__device__ int   g_srcs[NE];                // CSR column (source node ids)
__device__ int   g_bsum[128];               // per-block scan totals

__device__ __forceinline__ float lrelu(float v) { return v >= 0.f ? v : NEG * v; }
__device__ __forceinline__ int clampi(int v, int n) {
    return v < 0 ? 0 : (v >= n ? n - 1 : v);
}

// ---------------------------------------------------------------------------
// Kernel 0: transpose weights + zero degree counters
// ---------------------------------------------------------------------------
__global__ void __launch_bounds__(128) k_transpose(
    const float* __restrict__ lin_w, const float* __restrict__ res_w, int N)
{
    int k = blockIdx.x;      // 0..63
    int t = threadIdx.x;     // 0..127
    g_linwT[k * OUT_DIM + t] = lin_w[t * IN_CH + k];
    g_reswT[k * OUT_DIM + t] = res_w[t * IN_CH + k];
    for (int i = blockIdx.x * 128 + t; i < N; i += 64 * 128) g_deg[i] = 0;
}

// ---------------------------------------------------------------------------
// Kernel 1: per-node — xt = x @ lin_w^T, attention halves
// ---------------------------------------------------------------------------
__global__ void __launch_bounds__(128) k_node_prep(
    const float* __restrict__ x,
    const float* __restrict__ att_src, const float* __restrict__ att_dst, int N)
{
    int n = blockIdx.x;
    int t = threadIdx.x;
    if (n >= N) return;

    __shared__ float sx[IN_CH];
    if (t < IN_CH) sx[t] = x[n * IN_CH + t];
    __syncthreads();

    float acc = 0.f;
#pragma unroll
    for (int k = 0; k < IN_CH; k++) acc += sx[k] * g_linwT[k * OUT_DIM + t];

    g_xt[n * OUT_DIM + t] = acc;

    int h = t >> 5, c = t & 31;
    float as = acc * att_src[h * CPH + c];
    float ad = acc * att_dst[h * CPH + c];
#pragma unroll
    for (int o = 16; o; o >>= 1) {
        as += __shfl_xor_sync(0xFFFFFFFFu, as, o);
        ad += __shfl_xor_sync(0xFFFFFFFFu, ad, o);
    }
    if (c == 0) {
        g_asrc[n * HEADS + h] = as;
        g_adst[n * HEADS + h] = ad;
    }
}

// ---------------------------------------------------------------------------
// Kernel 2: count in-degrees
// ---------------------------------------------------------------------------
__global__ void __launch_bounds__(256) k_count(const int* __restrict__ ei, int E, int N)
{
    int e = blockIdx.x * blockDim.x + threadIdx.x;
    if (e >= E) return;
    int d = clampi(ei[E + e], N);
    atomicAdd(&g_deg[d], 1);
}

// ---------------------------------------------------------------------------
// Kernel 3a/3b/3c: chip-wide exclusive scan of degrees
// ---------------------------------------------------------------------------
__global__ void __launch_bounds__(SCAN_TILE) k_scan1(int N)
{
    int t = threadIdx.x;
    int i = blockIdx.x * SCAN_TILE + t;
    int v = (i < N) ? g_deg[i] : 0;

    int lane = t & 31, wid = t >> 5;
    int inc = v;
#pragma unroll
    for (int o = 1; o < 32; o <<= 1) {
        int u = __shfl_up_sync(0xFFFFFFFFu, inc, o);
        if (lane >= o) inc += u;
    }
    __shared__ int ws[16];
    if (lane == 31) ws[wid] = inc;
    __syncthreads();
    if (t < 16) {
        int s = ws[t];
        int inc2 = s;
#pragma unroll
        for (int o = 1; o < 16; o <<= 1) {
            int u = __shfl_up_sync(0xFFFFu, inc2, o);
            if (t >= o) inc2 += u;
        }
        ws[t] = inc2 - s;                    // exclusive warp offset
        if (t == 15) g_bsum[blockIdx.x] = inc2;   // block total
    }
    __syncthreads();
    if (i < N) g_rowptr[i] = inc - v + ws[wid];  // block-local exclusive
}

__global__ void __launch_bounds__(128) k_scan2(int NB)
{
    int t = threadIdx.x;
    int v = (t < NB) ? g_bsum[t] : 0;
    __shared__ int s[128];
    s[t] = v;
    __syncthreads();
    for (int off = 1; off < 128; off <<= 1) {
        int u = (t >= off) ? s[t - off] : 0;
        __syncthreads();
        s[t] += u;
        __syncthreads();
    }
    g_bsum[t] = s[t] - v;   // exclusive block offset
}

__global__ void __launch_bounds__(SCAN_TILE) k_scan3(int N)
{
    int i = blockIdx.x * SCAN_TILE + threadIdx.x;
    if (i >= N) return;
    int r = g_rowptr[i] + g_bsum[blockIdx.x];
    g_rowptr[i] = r;
    g_cursor[i] = r;
}

// ---------------------------------------------------------------------------
// Kernel 4: fill CSR columns
// ---------------------------------------------------------------------------
__global__ void __launch_bounds__(256) k_fill(const int* __restrict__ ei, int E, int N)
{
    int e = blockIdx.x * blockDim.x + threadIdx.x;
    if (e >= E) return;
    int s = clampi(ei[e], N);
    int d = clampi(ei[E + e], N);
    int p = atomicAdd(&g_cursor[d], 1);
    g_srcs[p] = s;
}

// ---------------------------------------------------------------------------
// Kernel 5: one warp per dst node — SINGLE-PASS aggregation:
//   acc = Σ_e exp(e)·xt[src];  exsum = Σ_e exp(e);  result = acc/exsum
// (valid because esum is constant per (dst,head) — no per-edge division)
// CSR indices batch-loaded 32 at a time, edge loop unrolled x2.
// Fused: self-loop, residual GEMV, LayerNorm, LeakyReLU, store.
// block = 256 (8 warps = 8 nodes), grid = ceil(N/8)
// ---------------------------------------------------------------------------
__global__ void __launch_bounds__(256) k_aggregate(
    const float* __restrict__ x,
    const float* __restrict__ res_b, const float* __restrict__ gat_bias,
    const float* __restrict__ ln_g, const float* __restrict__ ln_b,
    float* __restrict__ out, int N)
{
    int w    = threadIdx.x >> 5;
    int lane = threadIdx.x & 31;
    int d = blockIdx.x * 8 + w;
    if (d >= N) return;

    int r0 = g_rowptr[d];
    int r1 = g_cursor[d];          // == row end after fill

    int hB = lane >> 3;            // head for this lane's 4 channels
    float adst_hB = g_adst[d * HEADS + hB];

    // ---- single pass over in-edges ----
    float4 acc0 = make_float4(0.f, 0.f, 0.f, 0.f);
    float4 acc1 = make_float4(0.f, 0.f, 0.f, 0.f);
    float exsum0 = 0.f, exsum1 = 0.f;

    for (int base = r0; base < r1; base += 32) {
        int cnt = r1 - base; if (cnt > 32) cnt = 32;
        int idx = (base + lane < r1) ? g_srcs[base + lane] : 0;

        int j = 0;
        for (; j + 1 < cnt; j += 2) {
            int s0 = __shfl_sync(0xFFFFFFFFu, idx, j);
            int s1 = __shfl_sync(0xFFFFFFFFu, idx, j + 1);
            float ex0 = expf(lrelu(g_asrc[s0 * HEADS + hB] + adst_hB));
            float ex1 = expf(lrelu(g_asrc[s1 * HEADS + hB] + adst_hB));
            float4 v0 = *reinterpret_cast<const float4*>(g_xt + s0 * OUT_DIM + lane * 4);
            float4 v1 = *reinterpret_cast<const float4*>(g_xt + s1 * OUT_DIM + lane * 4);
            exsum0 += ex0; exsum1 += ex1;
            acc0.x += ex0 * v0.x; acc0.y += ex0 * v0.y;
            acc0.z += ex0 * v0.z; acc0.w += ex0 * v0.w;
            acc1.x += ex1 * v1.x; acc1.y += ex1 * v1.y;
            acc1.z += ex1 * v1.z; acc1.w += ex1 * v1.w;
        }
        if (j < cnt) {
            int s0 = __shfl_sync(0xFFFFFFFFu, idx, j);
            float ex0 = expf(lrelu(g_asrc[s0 * HEADS + hB] + adst_hB));
            float4 v0 = *reinterpret_cast<const float4*>(g_xt + s0 * OUT_DIM + lane * 4);
            exsum0 += ex0;
            acc0.x += ex0 * v0.x; acc0.y += ex0 * v0.y;
            acc0.z += ex0 * v0.z; acc0.w += ex0 * v0.w;
        }
    }

    // self-loop (uses this node's own asrc for head hB)
    {
        float ex = expf(lrelu(g_asrc[d * HEADS + hB] + adst_hB));
        float4 v = *reinterpret_cast<const float4*>(g_xt + d * OUT_DIM + lane * 4);
        exsum0 += ex;
        acc0.x += ex * v.x; acc0.y += ex * v.y;
        acc0.z += ex * v.z; acc0.w += ex * v.w;
    }

    float inv_es = 1.f / (exsum0 + exsum1 + 1e-16f);
    float4 acc;
    acc.x = (acc0.x + acc1.x) * inv_es;
    acc.y = (acc0.y + acc1.y) * inv_es;
    acc.z = (acc0.z + acc1.z) * inv_es;
    acc.w = (acc0.w + acc1.w) * inv_es;

    // ---- residual GEMV (per-warp smem x row, coalesced transposed weights) ----
    __shared__ float sx[8][IN_CH];
    sx[w][lane]      = x[d * IN_CH + lane];
    sx[w][lane + 32] = x[d * IN_CH + lane + 32];
    __syncwarp();

    float4 r = make_float4(0.f, 0.f, 0.f, 0.f);
#pragma unroll
    for (int k = 0; k < IN_CH; k++) {
        float xv = sx[w][k];
        float4 wv = *reinterpret_cast<const float4*>(g_reswT + k * OUT_DIM + lane * 4);
        r.x += xv * wv.x; r.y += xv * wv.y; r.z += xv * wv.z; r.w += xv * wv.w;
    }

    int t0 = lane * 4;
    float4 gb  = *reinterpret_cast<const float4*>(gat_bias + t0);
    float4 rb  = *reinterpret_cast<const float4*>(res_b + t0);
    float4 z;
    z.x = acc.x + gb.x + r.x + rb.x;
    z.y = acc.y + gb.y + r.y + rb.y;
    z.z = acc.z + gb.z + r.z + rb.z;
    z.w = acc.w + gb.w + r.w + rb.w;

    // ---- LayerNorm over 128 (warp reduce) ----
    float sum = z.x + z.y + z.z + z.w;
#pragma unroll
    for (int o = 16; o; o >>= 1) sum += __shfl_xor_sync(0xFFFFFFFFu, sum, o);
    float mu = sum * (1.f / OUT_DIM);

    float4 zc;
    zc.x = z.x - mu; zc.y = z.y - mu; zc.z = z.z - mu; zc.w = z.w - mu;
    float vv = zc.x * zc.x + zc.y * zc.y + zc.z * zc.z + zc.w * zc.w;
#pragma unroll
    for (int o = 16; o; o >>= 1) vv += __shfl_xor_sync(0xFFFFFFFFu, vv, o);
    float rs = rsqrtf(vv * (1.f / OUT_DIM) + 1e-5f);

    float4 lg = *reinterpret_cast<const float4*>(ln_g + t0);
    float4 lb = *reinterpret_cast<const float4*>(ln_b + t0);
    float4 o4;
    o4.x = lrelu(zc.x * rs * lg.x + lb.x);
    o4.y = lrelu(zc.y * rs * lg.y + lb.y);
    o4.z = lrelu(zc.z * rs * lg.z + lb.z);
    o4.w = lrelu(zc.w * rs * lg.w + lb.w);
    *reinterpret_cast<float4*>(out + d * OUT_DIM + t0) = o4;
}

// ---------------------------------------------------------------------------
extern "C" void kernel_launch(void* const* d_in, const int* in_sizes, int n_in,
                              void* d_out, int out_size)
{
    const float* x        = (const float*)d_in[0];
    const int*   ei       = (const int*)d_in[1];     // int32 (JAX x64 disabled)
    const float* lin_w    = (const float*)d_in[2];
    const float* att_src  = (const float*)d_in[3];
    const float* att_dst  = (const float*)d_in[4];
    const float* gat_bias = (const float*)d_in[5];
    const float* res_w    = (const float*)d_in[6];
    const float* res_b    = (const float*)d_in[7];
    const float* ln_g     = (const float*)d_in[8];
    const float* ln_b     = (const float*)d_in[9];
    float* out = (float*)d_out;

    int N = in_sizes[0] / IN_CH;     // 50000
    int E = in_sizes[1] / 2;         // 800000
    if (N > NN) N = NN;              // clamp to static scratch capacity
    if (E > NE) E = NE;

    int NB = (N + SCAN_TILE - 1) / SCAN_TILE;   // <= 98

    k_transpose<<<IN_CH, 128>>>(lin_w, res_w, N);
    k_node_prep<<<N, 128>>>(x, att_src, att_dst, N);
    k_count<<<(E + 255) / 256, 256>>>(ei, E, N);
    k_scan1<<<NB, SCAN_TILE>>>(N);
    k_scan2<<<1, 128>>>(NB);
    k_scan3<<<NB, SCAN_TILE>>>(N);
    k_fill<<<(E + 255) / 256, 256>>>(ei, E, N);
    k_aggregate<<<(N + 7) / 8, 256>>>(x, res_b, gat_bias, ln_g, ln_b, out, N);
}

// round 13
// speedup vs baseline: 1.7567x; 1.1409x over previous
#include <cuda_runtime.h>
#include <cuda_bf16.h>

// Problem constants (reference shapes are fixed)
#define NN 50000
#define NE 800000
#define IN_CH 64
#define OUT_DIM 128
#define HEADS 4
#define CPH 32           // channels per head
#define NEG 0.2f
#define SCAN_TILE 512

// Scratch (static __device__ — allocations are forbidden)
__device__ float g_xt[NN * OUT_DIM];        // transformed features [N,128] (25.6 MB)
__device__ float g_asrc[NN * HEADS];        // per-node src attention half
__device__ float g_adst[NN * HEADS];        // per-node dst attention half
__device__ float g_linwT[IN_CH * OUT_DIM];  // lin_w transposed [k][t]
__device__ float g_reswT[IN_CH * OUT_DIM];  // res_w transposed [k][t]
__device__ int   g_deg[NN];                 // in-degree per dst
__device__ int   g_rowptr[NN];              // CSR row start
__device__ int   g_cursor[NN];              // fill cursor (== row end after fill)
__device__ int   g_srcs[NE];                // CSR column (source node ids)
__device__ int   g_bsum[128];               // per-block scan totals

__device__ __forceinline__ float lrelu(float v) { return v >= 0.f ? v : NEG * v; }
__device__ __forceinline__ int clampi(int v, int n) {
    return v < 0 ? 0 : (v >= n ? n - 1 : v);
}

// ---------------------------------------------------------------------------
// Kernel 0: transpose weights + zero degree counters
// ---------------------------------------------------------------------------
__global__ void __launch_bounds__(128) k_transpose(
    const float* __restrict__ lin_w, const float* __restrict__ res_w, int N)
{
    int k = blockIdx.x;      // 0..63
    int t = threadIdx.x;     // 0..127
    g_linwT[k * OUT_DIM + t] = lin_w[t * IN_CH + k];
    g_reswT[k * OUT_DIM + t] = res_w[t * IN_CH + k];
    for (int i = blockIdx.x * 128 + t; i < N; i += 64 * 128) g_deg[i] = 0;
}

// ---------------------------------------------------------------------------
// Kernel 1: warp-per-node — xt = x @ lin_w^T (float4), attention halves
// block = 256 (8 warps = 8 nodes), grid = ceil(N/8)
// ---------------------------------------------------------------------------
__global__ void __launch_bounds__(256) k_node_prep(
    const float* __restrict__ x,
    const float* __restrict__ att_src, const float* __restrict__ att_dst, int N)
{
    int w    = threadIdx.x >> 5;
    int lane = threadIdx.x & 31;
    int n = blockIdx.x * 8 + w;
    if (n >= N) return;

    __shared__ float sx[8][IN_CH];
    sx[w][lane]      = x[n * IN_CH + lane];
    sx[w][lane + 32] = x[n * IN_CH + lane + 32];
    __syncwarp();

    float4 acc = make_float4(0.f, 0.f, 0.f, 0.f);
#pragma unroll
    for (int k = 0; k < IN_CH; k++) {
        float xv = sx[w][k];
        float4 wv = *reinterpret_cast<const float4*>(g_linwT + k * OUT_DIM + lane * 4);
        acc.x += xv * wv.x; acc.y += xv * wv.y;
        acc.z += xv * wv.z; acc.w += xv * wv.w;
    }
    *reinterpret_cast<float4*>(g_xt + n * OUT_DIM + lane * 4) = acc;

    // attention halves: lane owns channels [lane*4, lane*4+4) of head hB = lane>>3
    int hB = lane >> 3;
    int cg = (lane & 7) * 4;    // channel offset within head
    float4 s4 = *reinterpret_cast<const float4*>(att_src + hB * CPH + cg);
    float4 d4 = *reinterpret_cast<const float4*>(att_dst + hB * CPH + cg);
    float as = acc.x * s4.x + acc.y * s4.y + acc.z * s4.z + acc.w * s4.w;
    float ad = acc.x * d4.x + acc.y * d4.y + acc.z * d4.z + acc.w * d4.w;
#pragma unroll
    for (int o = 1; o < 8; o <<= 1) {
        as += __shfl_xor_sync(0xFFFFFFFFu, as, o);
        ad += __shfl_xor_sync(0xFFFFFFFFu, ad, o);
    }
    if ((lane & 7) == 0) {
        g_asrc[n * HEADS + hB] = as;
        g_adst[n * HEADS + hB] = ad;
    }
}

// ---------------------------------------------------------------------------
// Kernel 2: count in-degrees
// ---------------------------------------------------------------------------
__global__ void __launch_bounds__(256) k_count(const int* __restrict__ ei, int E, int N)
{
    int e = blockIdx.x * blockDim.x + threadIdx.x;
    if (e >= E) return;
    int d = clampi(ei[E + e], N);
    atomicAdd(&g_deg[d], 1);
}

// ---------------------------------------------------------------------------
// Kernel 3a/3b/3c: chip-wide exclusive scan of degrees
// ---------------------------------------------------------------------------
__global__ void __launch_bounds__(SCAN_TILE) k_scan1(int N)
{
    int t = threadIdx.x;
    int i = blockIdx.x * SCAN_TILE + t;
    int v = (i < N) ? g_deg[i] : 0;

    int lane = t & 31, wid = t >> 5;
    int inc = v;
#pragma unroll
    for (int o = 1; o < 32; o <<= 1) {
        int u = __shfl_up_sync(0xFFFFFFFFu, inc, o);
        if (lane >= o) inc += u;
    }
    __shared__ int ws[16];
    if (lane == 31) ws[wid] = inc;
    __syncthreads();
    if (t < 16) {
        int s = ws[t];
        int inc2 = s;
#pragma unroll
        for (int o = 1; o < 16; o <<= 1) {
            int u = __shfl_up_sync(0xFFFFu, inc2, o);
            if (t >= o) inc2 += u;
        }
        ws[t] = inc2 - s;                    // exclusive warp offset
        if (t == 15) g_bsum[blockIdx.x] = inc2;   // block total
    }
    __syncthreads();
    if (i < N) g_rowptr[i] = inc - v + ws[wid];  // block-local exclusive
}

__global__ void __launch_bounds__(128) k_scan2(int NB)
{
    int t = threadIdx.x;
    int v = (t < NB) ? g_bsum[t] : 0;
    __shared__ int s[128];
    s[t] = v;
    __syncthreads();
    for (int off = 1; off < 128; off <<= 1) {
        int u = (t >= off) ? s[t - off] : 0;
        __syncthreads();
        s[t] += u;
        __syncthreads();
    }
    g_bsum[t] = s[t] - v;   // exclusive block offset
}

__global__ void __launch_bounds__(SCAN_TILE) k_scan3(int N)
{
    int i = blockIdx.x * SCAN_TILE + threadIdx.x;
    if (i >= N) return;
    int r = g_rowptr[i] + g_bsum[blockIdx.x];
    g_rowptr[i] = r;
    g_cursor[i] = r;
}

// ---------------------------------------------------------------------------
// Kernel 4: fill CSR columns
// ---------------------------------------------------------------------------
__global__ void __launch_bounds__(256) k_fill(const int* __restrict__ ei, int E, int N)
{
    int e = blockIdx.x * blockDim.x + threadIdx.x;
    if (e >= E) return;
    int s = clampi(ei[e], N);
    int d = clampi(ei[E + e], N);
    int p = atomicAdd(&g_cursor[d], 1);
    g_srcs[p] = s;
}

// ---------------------------------------------------------------------------
// Kernel 5: one warp per dst node — single-pass weighted aggregation,
// unrolled x4 for load MLP; fused self-loop, residual GEMV, LN, LeakyReLU.
// block = 256 (8 warps = 8 nodes), grid = ceil(N/8)
// ---------------------------------------------------------------------------
__global__ void __launch_bounds__(256) k_aggregate(
    const float* __restrict__ x,
    const float* __restrict__ res_b, const float* __restrict__ gat_bias,
    const float* __restrict__ ln_g, const float* __restrict__ ln_b,
    float* __restrict__ out, int N)
{
    int w    = threadIdx.x >> 5;
    int lane = threadIdx.x & 31;
    int d = blockIdx.x * 8 + w;
    if (d >= N) return;

    int r0 = g_rowptr[d];
    int r1 = g_cursor[d];          // == row end after fill

    int hB = lane >> 3;            // head for this lane's 4 channels
    float adst_hB = g_adst[d * HEADS + hB];

    float4 acc0 = make_float4(0.f, 0.f, 0.f, 0.f);
    float4 acc1 = make_float4(0.f, 0.f, 0.f, 0.f);
    float4 acc2 = make_float4(0.f, 0.f, 0.f, 0.f);
    float4 acc3 = make_float4(0.f, 0.f, 0.f, 0.f);
    float exsum = 0.f;

    for (int base = r0; base < r1; base += 32) {
        int cnt = r1 - base; if (cnt > 32) cnt = 32;
        int idx = (base + lane < r1) ? g_srcs[base + lane] : 0;

        int j = 0;
        for (; j + 3 < cnt; j += 4) {
            int s0 = __shfl_sync(0xFFFFFFFFu, idx, j);
            int s1 = __shfl_sync(0xFFFFFFFFu, idx, j + 1);
            int s2 = __shfl_sync(0xFFFFFFFFu, idx, j + 2);
            int s3 = __shfl_sync(0xFFFFFFFFu, idx, j + 3);
            float a0 = g_asrc[s0 * HEADS + hB];
            float a1 = g_asrc[s1 * HEADS + hB];
            float a2 = g_asrc[s2 * HEADS + hB];
            float a3 = g_asrc[s3 * HEADS + hB];
            float4 v0 = *reinterpret_cast<const float4*>(g_xt + s0 * OUT_DIM + lane * 4);
            float4 v1 = *reinterpret_cast<const float4*>(g_xt + s1 * OUT_DIM + lane * 4);
            float4 v2 = *reinterpret_cast<const float4*>(g_xt + s2 * OUT_DIM + lane * 4);
            float4 v3 = *reinterpret_cast<const float4*>(g_xt + s3 * OUT_DIM + lane * 4);
            float ex0 = expf(lrelu(a0 + adst_hB));
            float ex1 = expf(lrelu(a1 + adst_hB));
            float ex2 = expf(lrelu(a2 + adst_hB));
            float ex3 = expf(lrelu(a3 + adst_hB));
            exsum += (ex0 + ex1) + (ex2 + ex3);
            acc0.x += ex0 * v0.x; acc0.y += ex0 * v0.y; acc0.z += ex0 * v0.z; acc0.w += ex0 * v0.w;
            acc1.x += ex1 * v1.x; acc1.y += ex1 * v1.y; acc1.z += ex1 * v1.z; acc1.w += ex1 * v1.w;
            acc2.x += ex2 * v2.x; acc2.y += ex2 * v2.y; acc2.z += ex2 * v2.z; acc2.w += ex2 * v2.w;
            acc3.x += ex3 * v3.x; acc3.y += ex3 * v3.y; acc3.z += ex3 * v3.z; acc3.w += ex3 * v3.w;
        }
        for (; j < cnt; j++) {
            int s0 = __shfl_sync(0xFFFFFFFFu, idx, j);
            float ex0 = expf(lrelu(g_asrc[s0 * HEADS + hB] + adst_hB));
            float4 v0 = *reinterpret_cast<const float4*>(g_xt + s0 * OUT_DIM + lane * 4);
            exsum += ex0;
            acc0.x += ex0 * v0.x; acc0.y += ex0 * v0.y;
            acc0.z += ex0 * v0.z; acc0.w += ex0 * v0.w;
        }
    }

    // self-loop
    {
        float ex = expf(lrelu(g_asrc[d * HEADS + hB] + adst_hB));
        float4 v = *reinterpret_cast<const float4*>(g_xt + d * OUT_DIM + lane * 4);
        exsum += ex;
        acc0.x += ex * v.x; acc0.y += ex * v.y;
        acc0.z += ex * v.z; acc0.w += ex * v.w;
    }

    float inv_es = 1.f / (exsum + 1e-16f);
    float4 acc;
    acc.x = ((acc0.x + acc1.x) + (acc2.x + acc3.x)) * inv_es;
    acc.y = ((acc0.y + acc1.y) + (acc2.y + acc3.y)) * inv_es;
    acc.z = ((acc0.z + acc1.z) + (acc2.z + acc3.z)) * inv_es;
    acc.w = ((acc0.w + acc1.w) + (acc2.w + acc3.w)) * inv_es;

    // ---- residual GEMV (per-warp smem x row, coalesced transposed weights) ----
    __shared__ float sx[8][IN_CH];
    sx[w][lane]      = x[d * IN_CH + lane];
    sx[w][lane + 32] = x[d * IN_CH + lane + 32];
    __syncwarp();

    float4 r = make_float4(0.f, 0.f, 0.f, 0.f);
#pragma unroll
    for (int k = 0; k < IN_CH; k++) {
        float xv = sx[w][k];
        float4 wv = *reinterpret_cast<const float4*>(g_reswT + k * OUT_DIM + lane * 4);
        r.x += xv * wv.x; r.y += xv * wv.y; r.z += xv * wv.z; r.w += xv * wv.w;
    }

    int t0 = lane * 4;
    float4 gb  = *reinterpret_cast<const float4*>(gat_bias + t0);
    float4 rb  = *reinterpret_cast<const float4*>(res_b + t0);
    float4 z;
    z.x = acc.x + gb.x + r.x + rb.x;
    z.y = acc.y + gb.y + r.y + rb.y;
    z.z = acc.z + gb.z + r.z + rb.z;
    z.w = acc.w + gb.w + r.w + rb.w;

    // ---- LayerNorm over 128 (warp reduce) ----
    float sum = z.x + z.y + z.z + z.w;
#pragma unroll
    for (int o = 16; o; o >>= 1) sum += __shfl_xor_sync(0xFFFFFFFFu, sum, o);
    float mu = sum * (1.f / OUT_DIM);

    float4 zc;
    zc.x = z.x - mu; zc.y = z.y - mu; zc.z = z.z - mu; zc.w = z.w - mu;
    float vv = zc.x * zc.x + zc.y * zc.y + zc.z * zc.z + zc.w * zc.w;
#pragma unroll
    for (int o = 16; o; o >>= 1) vv += __shfl_xor_sync(0xFFFFFFFFu, vv, o);
    float rs = rsqrtf(vv * (1.f / OUT_DIM) + 1e-5f);

    float4 lg = *reinterpret_cast<const float4*>(ln_g + t0);
    float4 lb = *reinterpret_cast<const float4*>(ln_b + t0);
    float4 o4;
    o4.x = lrelu(zc.x * rs * lg.x + lb.x);
    o4.y = lrelu(zc.y * rs * lg.y + lb.y);
    o4.z = lrelu(zc.z * rs * lg.z + lb.z);
    o4.w = lrelu(zc.w * rs * lg.w + lb.w);
    *reinterpret_cast<float4*>(out + d * OUT_DIM + t0) = o4;
}

// ---------------------------------------------------------------------------
extern "C" void kernel_launch(void* const* d_in, const int* in_sizes, int n_in,
                              void* d_out, int out_size)
{
    const float* x        = (const float*)d_in[0];
    const int*   ei       = (const int*)d_in[1];     // int32 (JAX x64 disabled)
    const float* lin_w    = (const float*)d_in[2];
    const float* att_src  = (const float*)d_in[3];
    const float* att_dst  = (const float*)d_in[4];
    const float* gat_bias = (const float*)d_in[5];
    const float* res_w    = (const float*)d_in[6];
    const float* res_b    = (const float*)d_in[7];
    const float* ln_g     = (const float*)d_in[8];
    const float* ln_b     = (const float*)d_in[9];
    float* out = (float*)d_out;

    int N = in_sizes[0] / IN_CH;     // 50000
    int E = in_sizes[1] / 2;         // 800000
    if (N > NN) N = NN;              // clamp to static scratch capacity
    if (E > NE) E = NE;

    int NB = (N + SCAN_TILE - 1) / SCAN_TILE;   // <= 98

    k_transpose<<<IN_CH, 128>>>(lin_w, res_w, N);
    k_node_prep<<<(N + 7) / 8, 256>>>(x, att_src, att_dst, N);
    k_count<<<(E + 255) / 256, 256>>>(ei, E, N);
    k_scan1<<<NB, SCAN_TILE>>>(N);
    k_scan2<<<1, 128>>>(NB);
    k_scan3<<<NB, SCAN_TILE>>>(N);
    k_fill<<<(E + 255) / 256, 256>>>(ei, E, N);
    k_aggregate<<<(N + 7) / 8, 256>>>(x, res_b, gat_bias, ln_g, ln_b, out, N);
}